// round 13
// baseline (speedup 1.0000x reference)
#include <cuda_runtime.h>
#include <cuda_fp16.h>
#include <cstdint>

#define HW 3136
#define EPS 1e-5f
#define NPATCH 3136   // 16 b * 4 g * 7 * 7

// Scratch (device globals: no runtime allocation allowed). fp16 intermediates.
__device__ __half g_mid1[16 * 128 * HW];
__device__ __half g_mid2[16 * 128 * HW];
__device__ int g_acnt[4];          // active count per group
__device__ int g_lista[4 * 784];   // per-group active patch ids

// ---- packed f32x2 helpers (sm_103a) ----
__device__ __forceinline__ unsigned long long pk2(float a, float b) {
    unsigned long long r;
    asm("mov.b64 %0, {%1, %2};" : "=l"(r) : "f"(a), "f"(b));
    return r;
}
__device__ __forceinline__ void fma2(unsigned long long& d, unsigned long long a,
                                     unsigned long long b) {
    asm("fma.rn.f32x2 %0, %1, %2, %0;" : "+l"(d) : "l"(a), "l"(b));
}
__device__ __forceinline__ float2 upk2(unsigned long long v) {
    float2 r;
    asm("mov.b64 {%0, %1}, %2;" : "=f"(r.x), "=f"(r.y) : "l"(v));
    return r;
}

// ---------------------------------------------------------------------------
// prep: bucket active patches by group (feeds k1/k2 only)
// ---------------------------------------------------------------------------
__global__ void prep(const float* __restrict__ mask) {
    __shared__ int cnt[4];
    int t = threadIdx.x;
    if (t < 4) cnt[t] = 0;
    __syncthreads();
    for (int i = t; i < NPATCH; i += blockDim.x) {
        int g = (i / 49) & 3;
        if (mask[i] != 0.f) {
            int p = atomicAdd(&cnt[g], 1);
            g_lista[g * 784 + p] = i;
        }
    }
    __syncthreads();
    if (t < 4) g_acnt[t] = cnt[t];
}

// ---------------------------------------------------------------------------
// zero_inactive: zero mid1 for inactive patches (k2 halo reads them).
// ---------------------------------------------------------------------------
__global__ __launch_bounds__(224) void zero_inactive(const float* __restrict__ mask) {
    const int t = threadIdx.x, blk = blockIdx.x;
    const int w = t >> 5, l = t & 31;
    const int packed = blk * 7 + w;
    if (mask[packed] != 0.f) return;
    const int pc = packed % 7;
    const int pr = (packed / 7) % 7;
    const int g = (packed / 49) & 3;
    const int b = packed / 196;
    const int r = l >> 2, cp = l & 3;
    __half* op = g_mid1 + (size_t)(b * 128 + g * 32) * HW + (pr * 8 + r) * 56 + pc * 8 + cp * 2;
    __half2 z = __floats2half2_rn(0.f, 0.f);
#pragma unroll
    for (int j = 0; j < 32; j++) *(__half2*)(op + (size_t)j * HW) = z;
}

// Common decode: 224 threads = 7 warps; warp takes an ACTIVE patch from its
// group's list. lane: r=l>>2 row, cp=l&3 col-pair; thread owns 2 pixels.

// ---------------------------------------------------------------------------
// K1: 1x1 conv (128 -> 16 oc per block) + BN1 + ReLU + mask premult -> fp16
// grid = 2 qc * 4 g * 112 pb; active patches only
// ---------------------------------------------------------------------------
__global__ __launch_bounds__(224, 3) void k1(const float* __restrict__ x,
                                             const float* __restrict__ mask,
                                             const float* __restrict__ w1,
                                             const float* __restrict__ bg1,
                                             const float* __restrict__ bb1,
                                             const float* __restrict__ bm1,
                                             const float* __restrict__ bv1) {
    __shared__ __align__(16) float ws[2048];  // [128 ic][16 oc]

    const int t = threadIdx.x, blk = blockIdx.x;
    const int qc = blk & 1;
    const int gb = blk >> 1;
    const int g = gb / 112, pb = gb % 112;
    const int nact = g_acnt[g];
    if (pb * 7 >= nact) return;

    for (int e = t; e < 2048; e += 224) {
        int j = e >> 7, ic = e & 127;
        ws[ic * 16 + j] = w1[(g * 32 + qc * 16 + j) * 128 + ic];
    }
    __syncthreads();

    const int w = t >> 5, l = t & 31;
    const int idx = pb * 7 + w;
    if (idx >= nact) return;
    const int packed = g_lista[g * 784 + idx];
    const int pc = packed % 7;
    const int pr = (packed / 7) % 7;
    const int b = packed / 196;
    const float m = mask[packed];

    const int r = l >> 2, cp = l & 3;
    const int grow = pr * 8 + r;
    const int col = pc * 8 + cp * 2;

    const float* xp = x + (size_t)(b * 512 + g * 128) * HW + grow * 56 + col;
    __half* op = g_mid1 + (size_t)(b * 128 + g * 32 + qc * 16) * HW + grow * 56 + col;

    unsigned long long A0[8], A1[8];
#pragma unroll
    for (int j = 0; j < 8; j++) { A0[j] = 0ull; A1[j] = 0ull; }

    for (int ic0 = 0; ic0 < 128; ic0 += 8) {
        float2 xv[8];
#pragma unroll
        for (int u = 0; u < 8; u++)
            xv[u] = *(const float2*)(xp + (size_t)(ic0 + u) * HW);
#pragma unroll
        for (int u = 0; u < 8; u++) {
            const unsigned long long* wf = (const unsigned long long*)(ws + (ic0 + u) * 16);
            unsigned long long xx0 = pk2(xv[u].x, xv[u].x);
            unsigned long long xx1 = pk2(xv[u].y, xv[u].y);
#pragma unroll
            for (int p = 0; p < 8; p++) {
                unsigned long long q = wf[p];
                fma2(A0[p], xx0, q);
                fma2(A1[p], xx1, q);
            }
        }
    }
#pragma unroll
    for (int p = 0; p < 8; p++) {
        float2 u0 = upk2(A0[p]);
        float2 u1 = upk2(A1[p]);
        float a0[2] = {u0.x, u0.y}, a1[2] = {u1.x, u1.y};
#pragma unroll
        for (int jj = 0; jj < 2; jj++) {
            int j = p * 2 + jj;
            int c = g * 32 + qc * 16 + j;
            float s = bg1[c] * rsqrtf(bv1[c] + EPS);
            float bb = bb1[c] - bm1[c] * s;
            float v0 = fmaxf(fmaf(m * a0[jj], s, bb), 0.f) * m;
            float v1 = fmaxf(fmaf(m * a1[jj], s, bb), 0.f) * m;
            *(__half2*)(op + (size_t)j * HW) = __floats2half2_rn(v0, v1);
        }
    }
}

// ---------------------------------------------------------------------------
// K2: 3x3 conv (32 -> 16 oc per block, pad 1) + BN2 + ReLU + mask -> fp16
// grid = 2 qc * 4 g * 112 pb; direct fp16 halo loads
// smem weights: [ic][tap k][16 oc]; tap k spans u64 slots [8k, 8k+8)
// ---------------------------------------------------------------------------
__global__ __launch_bounds__(224, 3) void k2(const float* __restrict__ mask,
                                             const float* __restrict__ w2,
                                             const float* __restrict__ bg2,
                                             const float* __restrict__ bb2,
                                             const float* __restrict__ bm2,
                                             const float* __restrict__ bv2) {
    __shared__ __align__(16) float ws[4608];  // [32 ic][9][16 oc]

    const int t = threadIdx.x, blk = blockIdx.x;
    const int qc = blk & 1;
    const int gb = blk >> 1;
    const int g = gb / 112, pb = gb % 112;
    const int nact = g_acnt[g];
    if (pb * 7 >= nact) return;

    for (int e = t; e < 4608; e += 224) {
        int j = e / 288;
        int rem = e - j * 288;
        int ic = rem / 9;
        int k = rem - ic * 9;
        ws[(ic * 9 + k) * 16 + j] = w2[((g * 32 + qc * 16 + j) * 32 + ic) * 9 + k];
    }
    __syncthreads();

    const int w = t >> 5, l = t & 31;
    const int idx = pb * 7 + w;
    if (idx >= nact) return;
    const int packed = g_lista[g * 784 + idx];
    const int pc = packed % 7;
    const int pr = (packed / 7) % 7;
    const int b = packed / 196;
    const float m = mask[packed];

    const int r = l >> 2, cp = l & 3;
    const int grow = pr * 8 + r;
    const int col = pc * 8 + cp * 2;

    __half* op = g_mid2 + (size_t)(b * 128 + g * 32 + qc * 16) * HW + grow * 56 + col;
    const __half* mb = g_mid1 + (size_t)(b * 128 + g * 32) * HW + grow * 56 + col;

    unsigned long long A0[8], A1[8];
#pragma unroll
    for (int j = 0; j < 8; j++) { A0[j] = 0ull; A1[j] = 0ull; }

#pragma unroll 2
    for (int ic = 0; ic < 32; ic++) {
        const __half* pic = mb + (size_t)ic * HW;
        float xm[3], x2[3];
        float2 xc[3];
#pragma unroll
        for (int dy = 0; dy < 3; dy++) {
            int yy = grow - 1 + dy;
            bool v = (yy >= 0) && (yy < 56);
            const __half* p = pic + (dy - 1) * 56;
            xm[dy] = (v && col > 0) ? __half2float(p[-1]) : 0.f;
            xc[dy] = v ? __half22float2(*(const __half2*)p) : make_float2(0.f, 0.f);
            x2[dy] = (v && col < 54) ? __half2float(p[2]) : 0.f;
        }
#pragma unroll
        for (int dy = 0; dy < 3; dy++) {
            const unsigned long long* wf = (const unsigned long long*)(ws + (ic * 9 + dy * 3) * 16);
            unsigned long long t00 = pk2(xm[dy], xm[dy]);
            unsigned long long t11 = pk2(xc[dy].x, xc[dy].x);
            unsigned long long t22 = pk2(xc[dy].y, xc[dy].y);
            unsigned long long t33 = pk2(x2[dy], x2[dy]);
#pragma unroll
            for (int p = 0; p < 8; p++) {
                unsigned long long w0 = wf[p];        // tap dx=0
                unsigned long long w1_ = wf[8 + p];   // tap dx=1
                unsigned long long w2_ = wf[16 + p];  // tap dx=2
                fma2(A0[p], t00, w0);
                fma2(A0[p], t11, w1_);
                fma2(A0[p], t22, w2_);
                fma2(A1[p], t11, w0);
                fma2(A1[p], t22, w1_);
                fma2(A1[p], t33, w2_);
            }
        }
    }
#pragma unroll
    for (int p = 0; p < 8; p++) {
        float2 u0 = upk2(A0[p]);
        float2 u1 = upk2(A1[p]);
        float a0[2] = {u0.x, u0.y}, a1[2] = {u1.x, u1.y};
#pragma unroll
        for (int jj = 0; jj < 2; jj++) {
            int j = p * 2 + jj;
            int c = g * 32 + qc * 16 + j;
            float s = bg2[c] * rsqrtf(bv2[c] + EPS);
            float bb = bb2[c] - bm2[c] * s;
            float v0 = fmaxf(fmaf(a0[jj], s, bb), 0.f) * m;
            float v1 = fmaxf(fmaf(a1[jj], s, bb), 0.f) * m;
            *(__half2*)(op + (size_t)j * HW) = __floats2half2_rn(v0, v1);
        }
    }
}

// ---------------------------------------------------------------------------
// K3: 1x1 conv (32 -> 16 oc per block) + BN3 + residual + ReLU (all patches)
// grid = (b, g, pr, qc in 0..7); mid2 read as fp16
// ---------------------------------------------------------------------------
__global__ __launch_bounds__(224, 3) void k3(const float* __restrict__ x,
                                             const float* __restrict__ mask,
                                             const float* __restrict__ w3,
                                             const float* __restrict__ bg3,
                                             const float* __restrict__ bb3,
                                             const float* __restrict__ bm3,
                                             const float* __restrict__ bv3,
                                             float* __restrict__ out) {
    __shared__ __align__(16) float ws[512];  // [32 ic][16 oc]

    const int t = threadIdx.x, blk = blockIdx.x;
    const int qc = blk & 7;
    const int rest = blk >> 3;
    const int pr = rest % 7;
    const int bg = rest / 7;
    const int g = bg & 3, b = bg >> 2;

    for (int e = t; e < 512; e += 224) {
        int j = e >> 5, ic = e & 31;
        ws[ic * 16 + j] = w3[(g * 128 + qc * 16 + j) * 32 + ic];
    }
    __syncthreads();

    const int w = t >> 5, l = t & 31;
    const int r = l >> 2, cp = l & 3;
    const int grow = pr * 8 + r;
    const int col = w * 8 + cp * 2;
    const float m = mask[((b * 4 + g) * 7 + pr) * 7 + w];

    const float* resp = x + (size_t)(b * 512 + g * 128 + qc * 16) * HW + grow * 56 + col;
    float* op = out + (size_t)(b * 512 + g * 128 + qc * 16) * HW + grow * 56 + col;

    float sc[16], bi[16];
#pragma unroll
    for (int j = 0; j < 16; j++) {
        int c = g * 128 + qc * 16 + j;
        float s = bg3[c] * rsqrtf(bv3[c] + EPS);
        sc[j] = s;
        bi[j] = bb3[c] - bm3[c] * s;
    }

    if (m != 0.f) {
        const __half* mp = g_mid2 + (size_t)(b * 128 + g * 32) * HW + grow * 56 + col;
        unsigned long long A0[8], A1[8];
#pragma unroll
        for (int j = 0; j < 8; j++) { A0[j] = 0ull; A1[j] = 0ull; }

        for (int ic0 = 0; ic0 < 32; ic0 += 8) {
            float2 xv[8];
#pragma unroll
            for (int u = 0; u < 8; u++)
                xv[u] = __half22float2(*(const __half2*)(mp + (size_t)(ic0 + u) * HW));
#pragma unroll
            for (int u = 0; u < 8; u++) {
                const unsigned long long* wf = (const unsigned long long*)(ws + (ic0 + u) * 16);
                unsigned long long xx0 = pk2(xv[u].x, xv[u].x);
                unsigned long long xx1 = pk2(xv[u].y, xv[u].y);
#pragma unroll
                for (int p = 0; p < 8; p++) {
                    unsigned long long q = wf[p];
                    fma2(A0[p], xx0, q);
                    fma2(A1[p], xx1, q);
                }
            }
        }
#pragma unroll
        for (int p = 0; p < 8; p++) {
            float2 u0 = upk2(A0[p]);
            float2 u1 = upk2(A1[p]);
            float a0[2] = {u0.x, u0.y}, a1[2] = {u1.x, u1.y};
#pragma unroll
            for (int jj = 0; jj < 2; jj++) {
                int j = p * 2 + jj;
                float2 res = *(const float2*)(resp + (size_t)j * HW);
                float v0 = fmaxf(fmaf(a0[jj], sc[j], bi[j]) + res.x, 0.f);
                float v1 = fmaxf(fmaf(a1[jj], sc[j], bi[j]) + res.y, 0.f);
                *(float2*)(op + (size_t)j * HW) = make_float2(v0, v1);
            }
        }
    } else {
#pragma unroll
        for (int j = 0; j < 16; j++) {
            float2 res = *(const float2*)(resp + (size_t)j * HW);
            float v0 = fmaxf(bi[j] + res.x, 0.f);
            float v1 = fmaxf(bi[j] + res.y, 0.f);
            *(float2*)(op + (size_t)j * HW) = make_float2(v0, v1);
        }
    }
}

// ---------------------------------------------------------------------------
extern "C" void kernel_launch(void* const* d_in, const int* in_sizes, int n_in,
                              void* d_out, int out_size) {
    const float* x    = (const float*)d_in[0];
    const float* mask = (const float*)d_in[1];
    const float* w1   = (const float*)d_in[2];
    const float* g1 = (const float*)d_in[3];
    const float* b1 = (const float*)d_in[4];
    const float* m1 = (const float*)d_in[5];
    const float* v1 = (const float*)d_in[6];
    const float* w2   = (const float*)d_in[7];
    const float* g2 = (const float*)d_in[8];
    const float* b2 = (const float*)d_in[9];
    const float* m2 = (const float*)d_in[10];
    const float* v2 = (const float*)d_in[11];
    const float* w3   = (const float*)d_in[12];
    const float* g3 = (const float*)d_in[13];
    const float* b3 = (const float*)d_in[14];
    const float* m3 = (const float*)d_in[15];
    const float* v3 = (const float*)d_in[16];
    float* out = (float*)d_out;

    prep<<<1, 1024>>>(mask);
    zero_inactive<<<448, 224>>>(mask);

    k1<<<2 * 4 * 112, 224>>>(x, mask, w1, g1, b1, m1, v1);
    k2<<<2 * 4 * 112, 224>>>(mask, w2, g2, b2, m2, v2);
    k3<<<16 * 4 * 7 * 8, 224>>>(x, mask, w3, g3, b3, m3, v3, out);
}

// round 14
// speedup vs baseline: 1.1069x; 1.1069x over previous
#include <cuda_runtime.h>
#include <cuda_fp16.h>
#include <cstdint>

#define HW 3136
#define EPS 1e-5f
#define NPATCH 3136   // 16 b * 4 g * 7 * 7

// Scratch (device globals: no runtime allocation allowed). fp16 intermediates.
__device__ __half g_mid1[16 * 128 * HW];
__device__ __half g_mid2[16 * 128 * HW];
__device__ int g_acnt[4];          // active count per group
__device__ int g_lista[4 * 784];   // per-group active patch ids

// ---- packed f32x2 helpers (sm_103a) ----
__device__ __forceinline__ unsigned long long pk2(float a, float b) {
    unsigned long long r;
    asm("mov.b64 %0, {%1, %2};" : "=l"(r) : "f"(a), "f"(b));
    return r;
}
__device__ __forceinline__ void fma2(unsigned long long& d, unsigned long long a,
                                     unsigned long long b) {
    asm("fma.rn.f32x2 %0, %1, %2, %0;" : "+l"(d) : "l"(a), "l"(b));
}
__device__ __forceinline__ float2 upk2(unsigned long long v) {
    float2 r;
    asm("mov.b64 {%0, %1}, %2;" : "=f"(r.x), "=f"(r.y) : "l"(v));
    return r;
}

// ---------------------------------------------------------------------------
// prep: bucket active patches by group (feeds k1/k2 only)
// ---------------------------------------------------------------------------
__global__ void prep(const float* __restrict__ mask) {
    __shared__ int cnt[4];
    int t = threadIdx.x;
    if (t < 4) cnt[t] = 0;
    __syncthreads();
    for (int i = t; i < NPATCH; i += blockDim.x) {
        int g = (i / 49) & 3;
        if (mask[i] != 0.f) {
            int p = atomicAdd(&cnt[g], 1);
            g_lista[g * 784 + p] = i;
        }
    }
    __syncthreads();
    if (t < 4) g_acnt[t] = cnt[t];
}

// ---------------------------------------------------------------------------
// zero_inactive: zero mid1 for inactive patches (k2 halo reads them).
// ---------------------------------------------------------------------------
__global__ __launch_bounds__(224) void zero_inactive(const float* __restrict__ mask) {
    const int t = threadIdx.x, blk = blockIdx.x;
    const int w = t >> 5, l = t & 31;
    const int packed = blk * 7 + w;
    if (mask[packed] != 0.f) return;
    const int pc = packed % 7;
    const int pr = (packed / 7) % 7;
    const int g = (packed / 49) & 3;
    const int b = packed / 196;
    const int r = l >> 2, cp = l & 3;
    __half* op = g_mid1 + (size_t)(b * 128 + g * 32) * HW + (pr * 8 + r) * 56 + pc * 8 + cp * 2;
    __half2 z = __floats2half2_rn(0.f, 0.f);
#pragma unroll
    for (int j = 0; j < 32; j++) *(__half2*)(op + (size_t)j * HW) = z;
}

// Common decode: 224 threads = 7 warps; warp takes an ACTIVE patch from its
// group's list. lane: r=l>>2 row, cp=l&3 col-pair; thread owns 2 pixels.

// ---------------------------------------------------------------------------
// K1: 1x1 conv (128 -> 8 oc per block) + BN1 + ReLU + mask premult -> fp16
// Software-pipelined: ping-pong register buffers over 8-ic chunks.
// grid = 4 qc * 4 g * 112 pb; active patches only
// ---------------------------------------------------------------------------
__global__ __launch_bounds__(224, 4) void k1(const float* __restrict__ x,
                                             const float* __restrict__ mask,
                                             const float* __restrict__ w1,
                                             const float* __restrict__ bg1,
                                             const float* __restrict__ bb1,
                                             const float* __restrict__ bm1,
                                             const float* __restrict__ bv1) {
    __shared__ __align__(16) float ws[1024];  // [ic][8]

    const int t = threadIdx.x, blk = blockIdx.x;
    const int qc = blk & 3;
    const int gb = blk >> 2;
    const int g = gb / 112, pb = gb % 112;
    const int nact = g_acnt[g];
    if (pb * 7 >= nact) return;

    for (int e = t; e < 1024; e += 224) {
        int j = e >> 7, ic = e & 127;
        ws[ic * 8 + j] = w1[(g * 32 + qc * 8 + j) * 128 + ic];
    }
    __syncthreads();

    const int w = t >> 5, l = t & 31;
    const int idx = pb * 7 + w;
    if (idx >= nact) return;
    const int packed = g_lista[g * 784 + idx];
    const int pc = packed % 7;
    const int pr = (packed / 7) % 7;
    const int b = packed / 196;
    const float m = mask[packed];

    const int r = l >> 2, cp = l & 3;
    const int grow = pr * 8 + r;
    const int col = pc * 8 + cp * 2;

    const float* xp = x + (size_t)(b * 512 + g * 128) * HW + grow * 56 + col;
    __half* op = g_mid1 + (size_t)(b * 128 + g * 32 + qc * 8) * HW + grow * 56 + col;

    unsigned long long A0[4], A1[4];
#pragma unroll
    for (int j = 0; j < 4; j++) { A0[j] = 0ull; A1[j] = 0ull; }

    float2 xa[8], xb[8];
#pragma unroll
    for (int u = 0; u < 8; u++) xa[u] = *(const float2*)(xp + (size_t)u * HW);

#pragma unroll
    for (int it = 0; it < 8; it++) {
        const int icA = it * 16;
        const int icB = icA + 8;
        // prefetch B-chunk while computing A-chunk
#pragma unroll
        for (int u = 0; u < 8; u++)
            xb[u] = *(const float2*)(xp + (size_t)(icB + u) * HW);
#pragma unroll
        for (int u = 0; u < 8; u++) {
            const ulonglong2* wp = (const ulonglong2*)(ws + (icA + u) * 8);
            ulonglong2 q0 = wp[0];
            ulonglong2 q1 = wp[1];
            unsigned long long xx0 = pk2(xa[u].x, xa[u].x);
            unsigned long long xx1 = pk2(xa[u].y, xa[u].y);
            fma2(A0[0], xx0, q0.x); fma2(A0[1], xx0, q0.y);
            fma2(A0[2], xx0, q1.x); fma2(A0[3], xx0, q1.y);
            fma2(A1[0], xx1, q0.x); fma2(A1[1], xx1, q0.y);
            fma2(A1[2], xx1, q1.x); fma2(A1[3], xx1, q1.y);
        }
        // prefetch next A-chunk while computing B-chunk
        if (it < 7) {
#pragma unroll
            for (int u = 0; u < 8; u++)
                xa[u] = *(const float2*)(xp + (size_t)(icA + 16 + u) * HW);
        }
#pragma unroll
        for (int u = 0; u < 8; u++) {
            const ulonglong2* wp = (const ulonglong2*)(ws + (icB + u) * 8);
            ulonglong2 q0 = wp[0];
            ulonglong2 q1 = wp[1];
            unsigned long long xx0 = pk2(xb[u].x, xb[u].x);
            unsigned long long xx1 = pk2(xb[u].y, xb[u].y);
            fma2(A0[0], xx0, q0.x); fma2(A0[1], xx0, q0.y);
            fma2(A0[2], xx0, q1.x); fma2(A0[3], xx0, q1.y);
            fma2(A1[0], xx1, q0.x); fma2(A1[1], xx1, q0.y);
            fma2(A1[2], xx1, q1.x); fma2(A1[3], xx1, q1.y);
        }
    }
#pragma unroll
    for (int p = 0; p < 4; p++) {
        float2 u0 = upk2(A0[p]);
        float2 u1 = upk2(A1[p]);
        float a0[2] = {u0.x, u0.y}, a1[2] = {u1.x, u1.y};
#pragma unroll
        for (int jj = 0; jj < 2; jj++) {
            int j = p * 2 + jj;
            int c = g * 32 + qc * 8 + j;
            float s = bg1[c] * rsqrtf(bv1[c] + EPS);
            float bb = bb1[c] - bm1[c] * s;
            float v0 = fmaxf(fmaf(m * a0[jj], s, bb), 0.f) * m;
            float v1 = fmaxf(fmaf(m * a1[jj], s, bb), 0.f) * m;
            *(__half2*)(op + (size_t)j * HW) = __floats2half2_rn(v0, v1);
        }
    }
}

// ---------------------------------------------------------------------------
// K2: 3x3 conv (32 -> 8 oc per block, pad 1) + BN2 + ReLU + mask -> fp16
// Software-pipelined over ic pairs with A/B row buffers.
// grid = 4 qc * 4 g * 112 pb
// ---------------------------------------------------------------------------
__global__ __launch_bounds__(224, 3) void k2(const float* __restrict__ mask,
                                             const float* __restrict__ w2,
                                             const float* __restrict__ bg2,
                                             const float* __restrict__ bb2,
                                             const float* __restrict__ bm2,
                                             const float* __restrict__ bv2) {
    __shared__ __align__(16) float ws[2304];  // [ic][9 tap][8 oc]

    const int t = threadIdx.x, blk = blockIdx.x;
    const int qc = blk & 3;
    const int gb = blk >> 2;
    const int g = gb / 112, pb = gb % 112;
    const int nact = g_acnt[g];
    if (pb * 7 >= nact) return;

    for (int e = t; e < 2304; e += 224) {
        int j = e / 288;
        int rem = e - j * 288;
        int ic = rem / 9;
        int k = rem - ic * 9;
        ws[(ic * 9 + k) * 8 + j] = w2[((g * 32 + qc * 8 + j) * 32 + ic) * 9 + k];
    }
    __syncthreads();

    const int w = t >> 5, l = t & 31;
    const int idx = pb * 7 + w;
    if (idx >= nact) return;
    const int packed = g_lista[g * 784 + idx];
    const int pc = packed % 7;
    const int pr = (packed / 7) % 7;
    const int b = packed / 196;
    const float m = mask[packed];

    const int r = l >> 2, cp = l & 3;
    const int grow = pr * 8 + r;
    const int col = pc * 8 + cp * 2;
    const bool vr0 = (grow > 0), vr2 = (grow < 55);
    const bool hasl = (col > 0), hasr = (col < 54);

    __half* op = g_mid2 + (size_t)(b * 128 + g * 32 + qc * 8) * HW + grow * 56 + col;
    const __half* mb = g_mid1 + (size_t)(b * 128 + g * 32) * HW + grow * 56 + col;

    unsigned long long A0[4], A1[4];
#pragma unroll
    for (int j = 0; j < 4; j++) { A0[j] = 0ull; A1[j] = 0ull; }

    auto ldrow = [&](int ic, float* xm, float2* xc, float* x2) {
        const __half* pic = mb + (size_t)ic * HW;
#pragma unroll
        for (int dy = 0; dy < 3; dy++) {
            bool v = (dy == 0) ? vr0 : ((dy == 2) ? vr2 : true);
            const __half* p = pic + (dy - 1) * 56;
            xm[dy] = (v && hasl) ? __half2float(p[-1]) : 0.f;
            xc[dy] = v ? __half22float2(*(const __half2*)p) : make_float2(0.f, 0.f);
            x2[dy] = (v && hasr) ? __half2float(p[2]) : 0.f;
        }
    };
    auto fmablk = [&](int ic, const float* xm, const float2* xc, const float* x2) {
#pragma unroll
        for (int dy = 0; dy < 3; dy++) {
            const ulonglong2* wp = (const ulonglong2*)(ws + (ic * 9 + dy * 3) * 8);
            ulonglong2 ta = wp[0];
            ulonglong2 tA = wp[1];
            ulonglong2 tb = wp[2];
            ulonglong2 tB = wp[3];
            ulonglong2 tc = wp[4];
            ulonglong2 tC = wp[5];
            unsigned long long t00 = pk2(xm[dy], xm[dy]);
            unsigned long long t11 = pk2(xc[dy].x, xc[dy].x);
            unsigned long long t22 = pk2(xc[dy].y, xc[dy].y);
            unsigned long long t33 = pk2(x2[dy], x2[dy]);
            fma2(A0[0], t00, ta.x); fma2(A0[1], t00, ta.y);
            fma2(A0[2], t00, tA.x); fma2(A0[3], t00, tA.y);
            fma2(A0[0], t11, tb.x); fma2(A0[1], t11, tb.y);
            fma2(A0[2], t11, tB.x); fma2(A0[3], t11, tB.y);
            fma2(A0[0], t22, tc.x); fma2(A0[1], t22, tc.y);
            fma2(A0[2], t22, tC.x); fma2(A0[3], t22, tC.y);
            fma2(A1[0], t11, ta.x); fma2(A1[1], t11, ta.y);
            fma2(A1[2], t11, tA.x); fma2(A1[3], t11, tA.y);
            fma2(A1[0], t22, tb.x); fma2(A1[1], t22, tb.y);
            fma2(A1[2], t22, tB.x); fma2(A1[3], t22, tB.y);
            fma2(A1[0], t33, tc.x); fma2(A1[1], t33, tc.y);
            fma2(A1[2], t33, tC.x); fma2(A1[3], t33, tC.y);
        }
    };

    float xmA[3], x2A[3], xmB[3], x2B[3];
    float2 xcA[3], xcB[3];
    ldrow(0, xmA, xcA, x2A);
#pragma unroll 1
    for (int ic = 0; ic < 32; ic += 2) {
        ldrow(ic + 1, xmB, xcB, x2B);     // prefetch odd ic
        fmablk(ic, xmA, xcA, x2A);
        if (ic + 2 < 32) ldrow(ic + 2, xmA, xcA, x2A);  // prefetch next even
        fmablk(ic + 1, xmB, xcB, x2B);
    }
#pragma unroll
    for (int p = 0; p < 4; p++) {
        float2 u0 = upk2(A0[p]);
        float2 u1 = upk2(A1[p]);
        float a0[2] = {u0.x, u0.y}, a1[2] = {u1.x, u1.y};
#pragma unroll
        for (int jj = 0; jj < 2; jj++) {
            int j = p * 2 + jj;
            int c = g * 32 + qc * 8 + j;
            float s = bg2[c] * rsqrtf(bv2[c] + EPS);
            float bb = bb2[c] - bm2[c] * s;
            float v0 = fmaxf(fmaf(a0[jj], s, bb), 0.f) * m;
            float v1 = fmaxf(fmaf(a1[jj], s, bb), 0.f) * m;
            *(__half2*)(op + (size_t)j * HW) = __floats2half2_rn(v0, v1);
        }
    }
}

// ---------------------------------------------------------------------------
// K3: 1x1 conv (32 -> 8 oc per block) + BN3 + residual + ReLU (all patches)
// Software-pipelined ping-pong over 8-ic chunks. grid = (b,g,pr,qc in 0..15)
// ---------------------------------------------------------------------------
__global__ __launch_bounds__(224, 4) void k3(const float* __restrict__ x,
                                             const float* __restrict__ mask,
                                             const float* __restrict__ w3,
                                             const float* __restrict__ bg3,
                                             const float* __restrict__ bb3,
                                             const float* __restrict__ bm3,
                                             const float* __restrict__ bv3,
                                             float* __restrict__ out) {
    __shared__ __align__(16) float ws[256];  // [ic][8]

    const int t = threadIdx.x, blk = blockIdx.x;
    const int qc = blk & 15;
    const int rest = blk >> 4;
    const int pr = rest % 7;
    const int bg = rest / 7;
    const int g = bg & 3, b = bg >> 2;

    for (int e = t; e < 256; e += 224) {
        int j = e >> 5, ic = e & 31;
        ws[ic * 8 + j] = w3[(g * 128 + qc * 8 + j) * 32 + ic];
    }
    __syncthreads();

    const int w = t >> 5, l = t & 31;
    const int r = l >> 2, cp = l & 3;
    const int grow = pr * 8 + r;
    const int col = w * 8 + cp * 2;
    const float m = mask[((b * 4 + g) * 7 + pr) * 7 + w];

    const float* resp = x + (size_t)(b * 512 + g * 128 + qc * 8) * HW + grow * 56 + col;
    float* op = out + (size_t)(b * 512 + g * 128 + qc * 8) * HW + grow * 56 + col;

    float sc[8], bi[8];
#pragma unroll
    for (int j = 0; j < 8; j++) {
        int c = g * 128 + qc * 8 + j;
        float s = bg3[c] * rsqrtf(bv3[c] + EPS);
        sc[j] = s;
        bi[j] = bb3[c] - bm3[c] * s;
    }

    if (m != 0.f) {
        const __half* mp = g_mid2 + (size_t)(b * 128 + g * 32) * HW + grow * 56 + col;
        unsigned long long A0[4], A1[4];
#pragma unroll
        for (int j = 0; j < 4; j++) { A0[j] = 0ull; A1[j] = 0ull; }

        float2 xa[8], xb[8];
#pragma unroll
        for (int u = 0; u < 8; u++)
            xa[u] = __half22float2(*(const __half2*)(mp + (size_t)u * HW));

#pragma unroll
        for (int it = 0; it < 2; it++) {
            const int icA = it * 16;
            const int icB = icA + 8;
#pragma unroll
            for (int u = 0; u < 8; u++)
                xb[u] = __half22float2(*(const __half2*)(mp + (size_t)(icB + u) * HW));
#pragma unroll
            for (int u = 0; u < 8; u++) {
                const ulonglong2* wp = (const ulonglong2*)(ws + (icA + u) * 8);
                ulonglong2 q0 = wp[0];
                ulonglong2 q1 = wp[1];
                unsigned long long xx0 = pk2(xa[u].x, xa[u].x);
                unsigned long long xx1 = pk2(xa[u].y, xa[u].y);
                fma2(A0[0], xx0, q0.x); fma2(A0[1], xx0, q0.y);
                fma2(A0[2], xx0, q1.x); fma2(A0[3], xx0, q1.y);
                fma2(A1[0], xx1, q0.x); fma2(A1[1], xx1, q0.y);
                fma2(A1[2], xx1, q1.x); fma2(A1[3], xx1, q1.y);
            }
            if (it < 1) {
#pragma unroll
                for (int u = 0; u < 8; u++)
                    xa[u] = __half22float2(*(const __half2*)(mp + (size_t)(icA + 16 + u) * HW));
            }
#pragma unroll
            for (int u = 0; u < 8; u++) {
                const ulonglong2* wp = (const ulonglong2*)(ws + (icB + u) * 8);
                ulonglong2 q0 = wp[0];
                ulonglong2 q1 = wp[1];
                unsigned long long xx0 = pk2(xb[u].x, xb[u].x);
                unsigned long long xx1 = pk2(xb[u].y, xb[u].y);
                fma2(A0[0], xx0, q0.x); fma2(A0[1], xx0, q0.y);
                fma2(A0[2], xx0, q1.x); fma2(A0[3], xx0, q1.y);
                fma2(A1[0], xx1, q0.x); fma2(A1[1], xx1, q0.y);
                fma2(A1[2], xx1, q1.x); fma2(A1[3], xx1, q1.y);
            }
        }
#pragma unroll
        for (int p = 0; p < 4; p++) {
            float2 u0 = upk2(A0[p]);
            float2 u1 = upk2(A1[p]);
            float a0[2] = {u0.x, u0.y}, a1[2] = {u1.x, u1.y};
#pragma unroll
            for (int jj = 0; jj < 2; jj++) {
                int j = p * 2 + jj;
                float2 res = *(const float2*)(resp + (size_t)j * HW);
                float v0 = fmaxf(fmaf(a0[jj], sc[j], bi[j]) + res.x, 0.f);
                float v1 = fmaxf(fmaf(a1[jj], sc[j], bi[j]) + res.y, 0.f);
                *(float2*)(op + (size_t)j * HW) = make_float2(v0, v1);
            }
        }
    } else {
#pragma unroll
        for (int j = 0; j < 8; j++) {
            float2 res = *(const float2*)(resp + (size_t)j * HW);
            float v0 = fmaxf(bi[j] + res.x, 0.f);
            float v1 = fmaxf(bi[j] + res.y, 0.f);
            *(float2*)(op + (size_t)j * HW) = make_float2(v0, v1);
        }
    }
}

// ---------------------------------------------------------------------------
extern "C" void kernel_launch(void* const* d_in, const int* in_sizes, int n_in,
                              void* d_out, int out_size) {
    const float* x    = (const float*)d_in[0];
    const float* mask = (const float*)d_in[1];
    const float* w1   = (const float*)d_in[2];
    const float* g1 = (const float*)d_in[3];
    const float* b1 = (const float*)d_in[4];
    const float* m1 = (const float*)d_in[5];
    const float* v1 = (const float*)d_in[6];
    const float* w2   = (const float*)d_in[7];
    const float* g2 = (const float*)d_in[8];
    const float* b2 = (const float*)d_in[9];
    const float* m2 = (const float*)d_in[10];
    const float* v2 = (const float*)d_in[11];
    const float* w3   = (const float*)d_in[12];
    const float* g3 = (const float*)d_in[13];
    const float* b3 = (const float*)d_in[14];
    const float* m3 = (const float*)d_in[15];
    const float* v3 = (const float*)d_in[16];
    float* out = (float*)d_out;

    prep<<<1, 1024>>>(mask);
    zero_inactive<<<448, 224>>>(mask);

    k1<<<4 * 4 * 112, 224>>>(x, mask, w1, g1, b1, m1, v1);
    k2<<<4 * 4 * 112, 224>>>(mask, w2, g2, b2, m2, v2);
    k3<<<16 * 4 * 7 * 16, 224>>>(x, mask, w3, g3, b3, m3, v3, out);
}

// round 15
// speedup vs baseline: 1.1155x; 1.0078x over previous
#include <cuda_runtime.h>
#include <cuda_fp16.h>
#include <cstdint>

#define HW 3136
#define EPS 1e-5f
#define NPATCH 3136   // 16 b * 4 g * 7 * 7

// Scratch (device globals: no runtime allocation allowed). fp16 intermediates.
__device__ __half g_mid1[16 * 128 * HW];
__device__ __half g_mid2[16 * 128 * HW];
__device__ int g_acnt[4];          // active count per group
__device__ int g_lista[4 * 784];   // per-group active patch ids

// ---- packed f32x2 helpers (sm_103a) ----
__device__ __forceinline__ unsigned long long pk2(float a, float b) {
    unsigned long long r;
    asm("mov.b64 %0, {%1, %2};" : "=l"(r) : "f"(a), "f"(b));
    return r;
}
__device__ __forceinline__ void fma2(unsigned long long& d, unsigned long long a,
                                     unsigned long long b) {
    asm("fma.rn.f32x2 %0, %1, %2, %0;" : "+l"(d) : "l"(a), "l"(b));
}
__device__ __forceinline__ float2 upk2(unsigned long long v) {
    float2 r;
    asm("mov.b64 {%0, %1}, %2;" : "=f"(r.x), "=f"(r.y) : "l"(v));
    return r;
}

// ---------------------------------------------------------------------------
// prep: bucket active patches by group (feeds k1/k2 only)
// ---------------------------------------------------------------------------
__global__ void prep(const float* __restrict__ mask) {
    __shared__ int cnt[4];
    int t = threadIdx.x;
    if (t < 4) cnt[t] = 0;
    __syncthreads();
    for (int i = t; i < NPATCH; i += blockDim.x) {
        int g = (i / 49) & 3;
        if (mask[i] != 0.f) {
            int p = atomicAdd(&cnt[g], 1);
            g_lista[g * 784 + p] = i;
        }
    }
    __syncthreads();
    if (t < 4) g_acnt[t] = cnt[t];
}

// ---------------------------------------------------------------------------
// zero_inactive: zero mid1 for inactive patches (k2 halo reads them).
// ---------------------------------------------------------------------------
__global__ __launch_bounds__(224) void zero_inactive(const float* __restrict__ mask) {
    const int t = threadIdx.x, blk = blockIdx.x;
    const int w = t >> 5, l = t & 31;
    const int packed = blk * 7 + w;
    if (mask[packed] != 0.f) return;
    const int pc = packed % 7;
    const int pr = (packed / 7) % 7;
    const int g = (packed / 49) & 3;
    const int b = packed / 196;
    const int r = l >> 2, cp = l & 3;
    __half* op = g_mid1 + (size_t)(b * 128 + g * 32) * HW + (pr * 8 + r) * 56 + pc * 8 + cp * 2;
    __half2 z = __floats2half2_rn(0.f, 0.f);
#pragma unroll
    for (int j = 0; j < 32; j++) *(__half2*)(op + (size_t)j * HW) = z;
}

// Common decode: 224 threads = 7 warps; warp takes an ACTIVE patch from its
// group's list. lane: r=l>>2 row, cp=l&3 col-pair; thread owns 2 pixels.

// ---------------------------------------------------------------------------
// K1: 1x1 conv (128 -> 8 oc per block) + BN1 + ReLU + mask premult -> fp16
// Software-pipelined: ping-pong register buffers over 8-ic chunks. (R14)
// grid = 4 qc * 4 g * 112 pb; active patches only
// ---------------------------------------------------------------------------
__global__ __launch_bounds__(224, 4) void k1(const float* __restrict__ x,
                                             const float* __restrict__ mask,
                                             const float* __restrict__ w1,
                                             const float* __restrict__ bg1,
                                             const float* __restrict__ bb1,
                                             const float* __restrict__ bm1,
                                             const float* __restrict__ bv1) {
    __shared__ __align__(16) float ws[1024];  // [ic][8]

    const int t = threadIdx.x, blk = blockIdx.x;
    const int qc = blk & 3;
    const int gb = blk >> 2;
    const int g = gb / 112, pb = gb % 112;
    const int nact = g_acnt[g];
    if (pb * 7 >= nact) return;

    for (int e = t; e < 1024; e += 224) {
        int j = e >> 7, ic = e & 127;
        ws[ic * 8 + j] = w1[(g * 32 + qc * 8 + j) * 128 + ic];
    }
    __syncthreads();

    const int w = t >> 5, l = t & 31;
    const int idx = pb * 7 + w;
    if (idx >= nact) return;
    const int packed = g_lista[g * 784 + idx];
    const int pc = packed % 7;
    const int pr = (packed / 7) % 7;
    const int b = packed / 196;
    const float m = mask[packed];

    const int r = l >> 2, cp = l & 3;
    const int grow = pr * 8 + r;
    const int col = pc * 8 + cp * 2;

    const float* xp = x + (size_t)(b * 512 + g * 128) * HW + grow * 56 + col;
    __half* op = g_mid1 + (size_t)(b * 128 + g * 32 + qc * 8) * HW + grow * 56 + col;

    unsigned long long A0[4], A1[4];
#pragma unroll
    for (int j = 0; j < 4; j++) { A0[j] = 0ull; A1[j] = 0ull; }

    float2 xa[8], xb[8];
#pragma unroll
    for (int u = 0; u < 8; u++) xa[u] = *(const float2*)(xp + (size_t)u * HW);

#pragma unroll
    for (int it = 0; it < 8; it++) {
        const int icA = it * 16;
        const int icB = icA + 8;
#pragma unroll
        for (int u = 0; u < 8; u++)
            xb[u] = *(const float2*)(xp + (size_t)(icB + u) * HW);
#pragma unroll
        for (int u = 0; u < 8; u++) {
            const ulonglong2* wp = (const ulonglong2*)(ws + (icA + u) * 8);
            ulonglong2 q0 = wp[0];
            ulonglong2 q1 = wp[1];
            unsigned long long xx0 = pk2(xa[u].x, xa[u].x);
            unsigned long long xx1 = pk2(xa[u].y, xa[u].y);
            fma2(A0[0], xx0, q0.x); fma2(A0[1], xx0, q0.y);
            fma2(A0[2], xx0, q1.x); fma2(A0[3], xx0, q1.y);
            fma2(A1[0], xx1, q0.x); fma2(A1[1], xx1, q0.y);
            fma2(A1[2], xx1, q1.x); fma2(A1[3], xx1, q1.y);
        }
        if (it < 7) {
#pragma unroll
            for (int u = 0; u < 8; u++)
                xa[u] = *(const float2*)(xp + (size_t)(icA + 16 + u) * HW);
        }
#pragma unroll
        for (int u = 0; u < 8; u++) {
            const ulonglong2* wp = (const ulonglong2*)(ws + (icB + u) * 8);
            ulonglong2 q0 = wp[0];
            ulonglong2 q1 = wp[1];
            unsigned long long xx0 = pk2(xb[u].x, xb[u].x);
            unsigned long long xx1 = pk2(xb[u].y, xb[u].y);
            fma2(A0[0], xx0, q0.x); fma2(A0[1], xx0, q0.y);
            fma2(A0[2], xx0, q1.x); fma2(A0[3], xx0, q1.y);
            fma2(A1[0], xx1, q0.x); fma2(A1[1], xx1, q0.y);
            fma2(A1[2], xx1, q1.x); fma2(A1[3], xx1, q1.y);
        }
    }
#pragma unroll
    for (int p = 0; p < 4; p++) {
        float2 u0 = upk2(A0[p]);
        float2 u1 = upk2(A1[p]);
        float a0[2] = {u0.x, u0.y}, a1[2] = {u1.x, u1.y};
#pragma unroll
        for (int jj = 0; jj < 2; jj++) {
            int j = p * 2 + jj;
            int c = g * 32 + qc * 8 + j;
            float s = bg1[c] * rsqrtf(bv1[c] + EPS);
            float bb = bb1[c] - bm1[c] * s;
            float v0 = fmaxf(fmaf(m * a0[jj], s, bb), 0.f) * m;
            float v1 = fmaxf(fmaf(m * a1[jj], s, bb), 0.f) * m;
            *(__half2*)(op + (size_t)j * HW) = __floats2half2_rn(v0, v1);
        }
    }
}

// ---------------------------------------------------------------------------
// K2: 3x3 conv (32 -> 8 oc per block, pad 1) + BN2 + ReLU + mask -> fp16 (R12)
// grid = 4 qc * 4 g * 112 pb; direct fp16 halo loads, unroll-2 ic loop
// ---------------------------------------------------------------------------
__global__ __launch_bounds__(224, 4) void k2(const float* __restrict__ mask,
                                             const float* __restrict__ w2,
                                             const float* __restrict__ bg2,
                                             const float* __restrict__ bb2,
                                             const float* __restrict__ bm2,
                                             const float* __restrict__ bv2) {
    __shared__ __align__(16) float ws[2304];  // [ic][9 tap][8 oc]

    const int t = threadIdx.x, blk = blockIdx.x;
    const int qc = blk & 3;
    const int gb = blk >> 2;
    const int g = gb / 112, pb = gb % 112;
    const int nact = g_acnt[g];
    if (pb * 7 >= nact) return;

    for (int e = t; e < 2304; e += 224) {
        int j = e / 288;
        int rem = e - j * 288;
        int ic = rem / 9;
        int k = rem - ic * 9;
        ws[(ic * 9 + k) * 8 + j] = w2[((g * 32 + qc * 8 + j) * 32 + ic) * 9 + k];
    }
    __syncthreads();

    const int w = t >> 5, l = t & 31;
    const int idx = pb * 7 + w;
    if (idx >= nact) return;
    const int packed = g_lista[g * 784 + idx];
    const int pc = packed % 7;
    const int pr = (packed / 7) % 7;
    const int b = packed / 196;
    const float m = mask[packed];

    const int r = l >> 2, cp = l & 3;
    const int grow = pr * 8 + r;
    const int col = pc * 8 + cp * 2;

    __half* op = g_mid2 + (size_t)(b * 128 + g * 32 + qc * 8) * HW + grow * 56 + col;
    const __half* mb = g_mid1 + (size_t)(b * 128 + g * 32) * HW + grow * 56 + col;

    unsigned long long A0[4], A1[4];
#pragma unroll
    for (int j = 0; j < 4; j++) { A0[j] = 0ull; A1[j] = 0ull; }

#pragma unroll 2
    for (int ic = 0; ic < 32; ic++) {
        const __half* pic = mb + (size_t)ic * HW;
        float xm[3], x2[3];
        float2 xc[3];
#pragma unroll
        for (int dy = 0; dy < 3; dy++) {
            int yy = grow - 1 + dy;
            bool v = (yy >= 0) && (yy < 56);
            const __half* p = pic + (dy - 1) * 56;
            xm[dy] = (v && col > 0) ? __half2float(p[-1]) : 0.f;
            xc[dy] = v ? __half22float2(*(const __half2*)p) : make_float2(0.f, 0.f);
            x2[dy] = (v && col < 54) ? __half2float(p[2]) : 0.f;
        }
#pragma unroll
        for (int dy = 0; dy < 3; dy++) {
            const ulonglong2* wp = (const ulonglong2*)(ws + (ic * 9 + dy * 3) * 8);
            ulonglong2 ta = wp[0];   // tap dx=0, oc pairs 0,1
            ulonglong2 tA = wp[1];   // tap dx=0, oc pairs 2,3
            ulonglong2 tb = wp[2];   // tap dx=1, oc pairs 0,1
            ulonglong2 tB = wp[3];   // tap dx=1, oc pairs 2,3
            ulonglong2 tc = wp[4];   // tap dx=2, oc pairs 0,1
            ulonglong2 tC = wp[5];   // tap dx=2, oc pairs 2,3
            unsigned long long t00 = pk2(xm[dy], xm[dy]);
            unsigned long long t11 = pk2(xc[dy].x, xc[dy].x);
            unsigned long long t22 = pk2(xc[dy].y, xc[dy].y);
            unsigned long long t33 = pk2(x2[dy], x2[dy]);
            fma2(A0[0], t00, ta.x); fma2(A0[1], t00, ta.y);
            fma2(A0[2], t00, tA.x); fma2(A0[3], t00, tA.y);
            fma2(A0[0], t11, tb.x); fma2(A0[1], t11, tb.y);
            fma2(A0[2], t11, tB.x); fma2(A0[3], t11, tB.y);
            fma2(A0[0], t22, tc.x); fma2(A0[1], t22, tc.y);
            fma2(A0[2], t22, tC.x); fma2(A0[3], t22, tC.y);
            fma2(A1[0], t11, ta.x); fma2(A1[1], t11, ta.y);
            fma2(A1[2], t11, tA.x); fma2(A1[3], t11, tA.y);
            fma2(A1[0], t22, tb.x); fma2(A1[1], t22, tb.y);
            fma2(A1[2], t22, tB.x); fma2(A1[3], t22, tB.y);
            fma2(A1[0], t33, tc.x); fma2(A1[1], t33, tc.y);
            fma2(A1[2], t33, tC.x); fma2(A1[3], t33, tC.y);
        }
    }
#pragma unroll
    for (int p = 0; p < 4; p++) {
        float2 u0 = upk2(A0[p]);
        float2 u1 = upk2(A1[p]);
        float a0[2] = {u0.x, u0.y}, a1[2] = {u1.x, u1.y};
#pragma unroll
        for (int jj = 0; jj < 2; jj++) {
            int j = p * 2 + jj;
            int c = g * 32 + qc * 8 + j;
            float s = bg2[c] * rsqrtf(bv2[c] + EPS);
            float bb = bb2[c] - bm2[c] * s;
            float v0 = fmaxf(fmaf(a0[jj], s, bb), 0.f) * m;
            float v1 = fmaxf(fmaf(a1[jj], s, bb), 0.f) * m;
            *(__half2*)(op + (size_t)j * HW) = __floats2half2_rn(v0, v1);
        }
    }
}

// ---------------------------------------------------------------------------
// K3: 1x1 conv (32 -> 8 oc per block) + BN3 + residual + ReLU (all patches)
// Software-pipelined ping-pong over 8-ic chunks. (R14)
// grid = (b,g,pr,qc in 0..15)
// ---------------------------------------------------------------------------
__global__ __launch_bounds__(224, 4) void k3(const float* __restrict__ x,
                                             const float* __restrict__ mask,
                                             const float* __restrict__ w3,
                                             const float* __restrict__ bg3,
                                             const float* __restrict__ bb3,
                                             const float* __restrict__ bm3,
                                             const float* __restrict__ bv3,
                                             float* __restrict__ out) {
    __shared__ __align__(16) float ws[256];  // [ic][8]

    const int t = threadIdx.x, blk = blockIdx.x;
    const int qc = blk & 15;
    const int rest = blk >> 4;
    const int pr = rest % 7;
    const int bg = rest / 7;
    const int g = bg & 3, b = bg >> 2;

    for (int e = t; e < 256; e += 224) {
        int j = e >> 5, ic = e & 31;
        ws[ic * 8 + j] = w3[(g * 128 + qc * 8 + j) * 32 + ic];
    }
    __syncthreads();

    const int w = t >> 5, l = t & 31;
    const int r = l >> 2, cp = l & 3;
    const int grow = pr * 8 + r;
    const int col = w * 8 + cp * 2;
    const float m = mask[((b * 4 + g) * 7 + pr) * 7 + w];

    const float* resp = x + (size_t)(b * 512 + g * 128 + qc * 8) * HW + grow * 56 + col;
    float* op = out + (size_t)(b * 512 + g * 128 + qc * 8) * HW + grow * 56 + col;

    float sc[8], bi[8];
#pragma unroll
    for (int j = 0; j < 8; j++) {
        int c = g * 128 + qc * 8 + j;
        float s = bg3[c] * rsqrtf(bv3[c] + EPS);
        sc[j] = s;
        bi[j] = bb3[c] - bm3[c] * s;
    }

    if (m != 0.f) {
        const __half* mp = g_mid2 + (size_t)(b * 128 + g * 32) * HW + grow * 56 + col;
        unsigned long long A0[4], A1[4];
#pragma unroll
        for (int j = 0; j < 4; j++) { A0[j] = 0ull; A1[j] = 0ull; }

        float2 xa[8], xb[8];
#pragma unroll
        for (int u = 0; u < 8; u++)
            xa[u] = __half22float2(*(const __half2*)(mp + (size_t)u * HW));

#pragma unroll
        for (int it = 0; it < 2; it++) {
            const int icA = it * 16;
            const int icB = icA + 8;
#pragma unroll
            for (int u = 0; u < 8; u++)
                xb[u] = __half22float2(*(const __half2*)(mp + (size_t)(icB + u) * HW));
#pragma unroll
            for (int u = 0; u < 8; u++) {
                const ulonglong2* wp = (const ulonglong2*)(ws + (icA + u) * 8);
                ulonglong2 q0 = wp[0];
                ulonglong2 q1 = wp[1];
                unsigned long long xx0 = pk2(xa[u].x, xa[u].x);
                unsigned long long xx1 = pk2(xa[u].y, xa[u].y);
                fma2(A0[0], xx0, q0.x); fma2(A0[1], xx0, q0.y);
                fma2(A0[2], xx0, q1.x); fma2(A0[3], xx0, q1.y);
                fma2(A1[0], xx1, q0.x); fma2(A1[1], xx1, q0.y);
                fma2(A1[2], xx1, q1.x); fma2(A1[3], xx1, q1.y);
            }
            if (it < 1) {
#pragma unroll
                for (int u = 0; u < 8; u++)
                    xa[u] = __half22float2(*(const __half2*)(mp + (size_t)(icA + 16 + u) * HW));
            }
#pragma unroll
            for (int u = 0; u < 8; u++) {
                const ulonglong2* wp = (const ulonglong2*)(ws + (icB + u) * 8);
                ulonglong2 q0 = wp[0];
                ulonglong2 q1 = wp[1];
                unsigned long long xx0 = pk2(xb[u].x, xb[u].x);
                unsigned long long xx1 = pk2(xb[u].y, xb[u].y);
                fma2(A0[0], xx0, q0.x); fma2(A0[1], xx0, q0.y);
                fma2(A0[2], xx0, q1.x); fma2(A0[3], xx0, q1.y);
                fma2(A1[0], xx1, q0.x); fma2(A1[1], xx1, q0.y);
                fma2(A1[2], xx1, q1.x); fma2(A1[3], xx1, q1.y);
            }
        }
#pragma unroll
        for (int p = 0; p < 4; p++) {
            float2 u0 = upk2(A0[p]);
            float2 u1 = upk2(A1[p]);
            float a0[2] = {u0.x, u0.y}, a1[2] = {u1.x, u1.y};
#pragma unroll
            for (int jj = 0; jj < 2; jj++) {
                int j = p * 2 + jj;
                float2 res = *(const float2*)(resp + (size_t)j * HW);
                float v0 = fmaxf(fmaf(a0[jj], sc[j], bi[j]) + res.x, 0.f);
                float v1 = fmaxf(fmaf(a1[jj], sc[j], bi[j]) + res.y, 0.f);
                *(float2*)(op + (size_t)j * HW) = make_float2(v0, v1);
            }
        }
    } else {
#pragma unroll
        for (int j = 0; j < 8; j++) {
            float2 res = *(const float2*)(resp + (size_t)j * HW);
            float v0 = fmaxf(bi[j] + res.x, 0.f);
            float v1 = fmaxf(bi[j] + res.y, 0.f);
            *(float2*)(op + (size_t)j * HW) = make_float2(v0, v1);
        }
    }
}

// ---------------------------------------------------------------------------
extern "C" void kernel_launch(void* const* d_in, const int* in_sizes, int n_in,
                              void* d_out, int out_size) {
    const float* x    = (const float*)d_in[0];
    const float* mask = (const float*)d_in[1];
    const float* w1   = (const float*)d_in[2];
    const float* g1 = (const float*)d_in[3];
    const float* b1 = (const float*)d_in[4];
    const float* m1 = (const float*)d_in[5];
    const float* v1 = (const float*)d_in[6];
    const float* w2   = (const float*)d_in[7];
    const float* g2 = (const float*)d_in[8];
    const float* b2 = (const float*)d_in[9];
    const float* m2 = (const float*)d_in[10];
    const float* v2 = (const float*)d_in[11];
    const float* w3   = (const float*)d_in[12];
    const float* g3 = (const float*)d_in[13];
    const float* b3 = (const float*)d_in[14];
    const float* m3 = (const float*)d_in[15];
    const float* v3 = (const float*)d_in[16];
    float* out = (float*)d_out;

    prep<<<1, 1024>>>(mask);
    zero_inactive<<<448, 224>>>(mask);

    k1<<<4 * 4 * 112, 224>>>(x, mask, w1, g1, b1, m1, v1);
    k2<<<4 * 4 * 112, 224>>>(mask, w2, g2, b2, m2, v2);
    k3<<<16 * 4 * 7 * 16, 224>>>(x, mask, w3, g3, b3, m3, v3, out);
}